// round 1
// baseline (speedup 1.0000x reference)
#include <cuda_runtime.h>
#include <math.h>

#define C64   64
#define K2    9
#define HI    256
#define WI    256
#define HO    512
#define WO    512
#define NPIX  (HO*WO)          // 262144
#define PPB   64               // pixels per block
#define NTH   256
#define H2S   260              // h2 smem row stride (floats), 16B-aligned, conflict-free
#define XCS   68               // xc smem row stride

struct __align__(16) Smem {
    float pose[3][PPB];        // 768 B
    int   iy[PPB];             // 256 B
    int   ix[PPB];             // 256 B
    float h1[PPB][64];         // 16384 B
    float h2[PPB][H2S];        // 66560 B
    float xc[PPB][XCS];        // 17408 B
};                              // total 101632 B

__device__ __forceinline__ float dot4(float4 w, float4 h, float a) {
    a = fmaf(w.x, h.x, a);
    a = fmaf(w.y, h.y, a);
    a = fmaf(w.z, h.z, a);
    a = fmaf(w.w, h.w, a);
    return a;
}

// ---- per-pixel MLP layer 1: h1[p][o] = relu(W1[o,:3] @ pose[:,p] + b1[o]) ----
__device__ __forceinline__ void mlp_h1(Smem& s, const float* __restrict__ w1,
                                       const float* __restrict__ b1, int tid) {
    int o  = tid & 63;
    int pb = tid >> 6;              // 4 groups of 16 pixels
    float wa = __ldg(w1 + o * 3 + 0);
    float wb = __ldg(w1 + o * 3 + 1);
    float wc = __ldg(w1 + o * 3 + 2);
    float bb = __ldg(b1 + o);
    #pragma unroll 4
    for (int p = pb * 16; p < pb * 16 + 16; p++) {
        float v = fmaf(wa, s.pose[0][p],
                  fmaf(wb, s.pose[1][p],
                  fmaf(wc, s.pose[2][p], bb)));
        s.h1[p][o] = fmaxf(v, 0.f);
    }
}

// ---- per-pixel MLP layer 2: h2[p][o] = relu(W2[o,:64] @ h1[p,:] + b2[o]) ----
__device__ __forceinline__ void mlp_h2(Smem& s, const float* __restrict__ w2,
                                       const float* __restrict__ b2, int tid) {
    int o = tid;                    // 256 outputs, one per thread
    float bb = __ldg(b2 + o);
    const float* wrow = w2 + o * 64;
    for (int pc = 0; pc < PPB; pc += 16) {
        float acc[16];
        #pragma unroll
        for (int j = 0; j < 16; j++) acc[j] = bb;
        #pragma unroll 4
        for (int kk = 0; kk < 64; kk++) {
            float w = __ldg(wrow + kk);
            #pragma unroll
            for (int j = 0; j < 16; j++)
                acc[j] = fmaf(w, s.h1[pc + j][kk], acc[j]);
        }
        #pragma unroll
        for (int j = 0; j < 16; j++)
            s.h2[pc + j][o] = fmaxf(acc[j], 0.f);
    }
}

__global__ void __launch_bounds__(NTH)
biupsampler_fused(const float* __restrict__ x,
                  const float* __restrict__ poseMap,
                  const int*   __restrict__ imY,
                  const int*   __restrict__ imX,
                  const float* __restrict__ sigmar,
                  const float* __restrict__ dw_w1, const float* __restrict__ dw_b1,
                  const float* __restrict__ dw_w2, const float* __restrict__ dw_b2,
                  const float* __restrict__ dw_w3, const float* __restrict__ dw_b3,
                  const float* __restrict__ pw_w1, const float* __restrict__ pw_b1,
                  const float* __restrict__ pw_w2, const float* __restrict__ pw_b2,
                  const float* __restrict__ pw_w3, const float* __restrict__ pw_b3,
                  float* __restrict__ out)
{
    extern __shared__ __align__(16) unsigned char smem_raw[];
    Smem& s = *reinterpret_cast<Smem*>(smem_raw);

    const int tid  = threadIdx.x;
    const int pix0 = blockIdx.x * PPB;

    // ---- stage 0: load pose + gather maps ----
    for (int i = tid; i < 3 * PPB; i += NTH) {
        int j = i / PPB, p = i % PPB;
        s.pose[j][p] = __ldg(poseMap + j * NPIX + pix0 + p);
    }
    if (tid < PPB)           s.iy[tid]        = __ldg(imY + pix0 + tid);
    else if (tid < 2 * PPB)  s.ix[tid - PPB]  = __ldg(imX + pix0 + tid - PPB);
    __syncthreads();

    // ===================== DW branch =====================
    mlp_h1(s, dw_w1, dw_b1, tid);
    __syncthreads();
    mlp_h2(s, dw_w2, dw_b2, tid);
    __syncthreads();

    // ---- pass 1: dw = W3 @ h2, gather, double softmax -> xc ----
    {
        const int cth   = tid & 15;     // 16 channel-threads
        const int pg    = tid >> 4;     // 16 pixel-groups of 4 pixels
        const int pbase = pg * 4;
        const float4* h2r0 = reinterpret_cast<const float4*>(s.h2[pbase + 0]);
        const float4* h2r1 = reinterpret_cast<const float4*>(s.h2[pbase + 1]);
        const float4* h2r2 = reinterpret_cast<const float4*>(s.h2[pbase + 2]);
        const float4* h2r3 = reinterpret_cast<const float4*>(s.h2[pbase + 3]);

        for (int ci = 0; ci < 4; ci++) {
            const int c = cth * 4 + ci;
            const float4* wr = reinterpret_cast<const float4*>(dw_w3 + c * 9 * 256);

            float acc[9][4];
            #pragma unroll
            for (int t = 0; t < 9; t++) {
                float b = __ldg(dw_b3 + c * 9 + t);
                acc[t][0] = b; acc[t][1] = b; acc[t][2] = b; acc[t][3] = b;
            }

            #pragma unroll 2
            for (int k4 = 0; k4 < 64; k4++) {
                float4 h0 = h2r0[k4];
                float4 h1v = h2r1[k4];
                float4 h2v = h2r2[k4];
                float4 h3v = h2r3[k4];
                #pragma unroll
                for (int t = 0; t < 9; t++) {
                    float4 w = __ldg(wr + t * 64 + k4);
                    acc[t][0] = dot4(w, h0,  acc[t][0]);
                    acc[t][1] = dot4(w, h1v, acc[t][1]);
                    acc[t][2] = dot4(w, h2v, acc[t][2]);
                    acc[t][3] = dot4(w, h3v, acc[t][3]);
                }
            }

            const float sg = __ldg(sigmar + c);
            const float* xc_base = x + c * (HI * WI);

            #pragma unroll
            for (int j = 0; j < 4; j++) {
                const int p  = pbase + j;
                const int iy = s.iy[p];
                const int ix = s.ix[p];

                float dwv[9], h[9];
                #pragma unroll
                for (int t = 0; t < 9; t++) dwv[t] = acc[t][j];

                #pragma unroll
                for (int t = 0; t < 9; t++) {
                    int yy = iy + t / 3 - 1;
                    int xx = ix + t % 3 - 1;
                    bool ok = ((unsigned)yy < HI) && ((unsigned)xx < WI);
                    h[t] = ok ? __ldg(xc_base + yy * WI + xx) : 0.f;
                }

                // softmax(dw) -> mean
                float m = dwv[0];
                #pragma unroll
                for (int t = 1; t < 9; t++) m = fmaxf(m, dwv[t]);
                float e[9], es = 0.f, hm = 0.f;
                #pragma unroll
                for (int t = 0; t < 9; t++) {
                    e[t] = __expf(dwv[t] - m);
                    es += e[t];
                    hm  = fmaf(h[t], e[t], hm);
                }
                float mean = hm / es;

                // bw = dw + sigmar*(h-mean)^2 ; softmax(bw) weighted sum
                float bw[9], m2 = -3.4e38f;
                #pragma unroll
                for (int t = 0; t < 9; t++) {
                    float d = h[t] - mean;
                    bw[t] = fmaf(sg * d, d, dwv[t]);
                    m2 = fmaxf(m2, bw[t]);
                }
                float s2 = 0.f, xcv = 0.f;
                #pragma unroll
                for (int t = 0; t < 9; t++) {
                    float ee = __expf(bw[t] - m2);
                    s2  += ee;
                    xcv  = fmaf(h[t], ee, xcv);
                }
                s.xc[p][c] = xcv / s2;
            }
        }
    }
    __syncthreads();

    // ===================== PW branch =====================
    mlp_h1(s, pw_w1, pw_b1, tid);
    __syncthreads();
    mlp_h2(s, pw_w2, pw_b2, tid);
    __syncthreads();

    // ---- pass 2: pw = PW3 @ h2p, contract with xc, reduce over c ----
    {
        const int p = tid >> 2;     // 64 pixels
        const int q = tid & 3;      // 4 channel-quarters (16 channels each)
        const float4* hrow = reinterpret_cast<const float4*>(s.h2[p]);

        float o0 = 0.f, o1 = 0.f, o2 = 0.f;
        for (int ci = 0; ci < 16; ci++) {
            const int c = q * 16 + ci;
            const float4* wr = reinterpret_cast<const float4*>(pw_w3 + c * 3 * 256);
            float a0 = __ldg(pw_b3 + c * 3 + 0);
            float a1 = __ldg(pw_b3 + c * 3 + 1);
            float a2 = __ldg(pw_b3 + c * 3 + 2);
            #pragma unroll 2
            for (int k4 = 0; k4 < 64; k4++) {
                float4 h  = hrow[k4];
                float4 wa = __ldg(wr + k4);
                float4 wb = __ldg(wr + 64 + k4);
                float4 wc = __ldg(wr + 128 + k4);
                a0 = dot4(wa, h, a0);
                a1 = dot4(wb, h, a1);
                a2 = dot4(wc, h, a2);
            }
            const float xcv = s.xc[p][c];
            o0 = fmaf(xcv, a0, o0);
            o1 = fmaf(xcv, a1, o1);
            o2 = fmaf(xcv, a2, o2);
        }

        // reduce over the 4 channel-quarters (4 consecutive lanes)
        const unsigned mask = 0xffffffffu;
        o0 += __shfl_xor_sync(mask, o0, 1);
        o0 += __shfl_xor_sync(mask, o0, 2);
        o1 += __shfl_xor_sync(mask, o1, 1);
        o1 += __shfl_xor_sync(mask, o1, 2);
        o2 += __shfl_xor_sync(mask, o2, 1);
        o2 += __shfl_xor_sync(mask, o2, 2);

        if (q == 0) {
            const int pix = pix0 + p;
            out[0 * NPIX + pix] = o0;
            out[1 * NPIX + pix] = o1;
            out[2 * NPIX + pix] = o2;
        }
    }
}

extern "C" void kernel_launch(void* const* d_in, const int* in_sizes, int n_in,
                              void* d_out, int out_size) {
    (void)in_sizes; (void)n_in; (void)out_size;
    const float* x      = (const float*)d_in[0];
    const float* pose   = (const float*)d_in[1];
    const int*   imY    = (const int*)  d_in[2];
    const int*   imX    = (const int*)  d_in[3];
    const float* sigmar = (const float*)d_in[4];
    const float* dw_w1  = (const float*)d_in[5];
    const float* dw_b1  = (const float*)d_in[6];
    const float* dw_w2  = (const float*)d_in[7];
    const float* dw_b2  = (const float*)d_in[8];
    const float* dw_w3  = (const float*)d_in[9];
    const float* dw_b3  = (const float*)d_in[10];
    const float* pw_w1  = (const float*)d_in[11];
    const float* pw_b1  = (const float*)d_in[12];
    const float* pw_w2  = (const float*)d_in[13];
    const float* pw_b2  = (const float*)d_in[14];
    const float* pw_w3  = (const float*)d_in[15];
    const float* pw_b3  = (const float*)d_in[16];
    float* out = (float*)d_out;

    const int smem = (int)sizeof(Smem);
    cudaFuncSetAttribute(biupsampler_fused,
                         cudaFuncAttributeMaxDynamicSharedMemorySize, smem);

    biupsampler_fused<<<NPIX / PPB, NTH, smem>>>(
        x, pose, imY, imX, sigmar,
        dw_w1, dw_b1, dw_w2, dw_b2, dw_w3, dw_b3,
        pw_w1, pw_b1, pw_w2, pw_b2, pw_w3, pw_b3,
        out);
}

// round 3
// speedup vs baseline: 3.3230x; 3.3230x over previous
#include <cuda_runtime.h>
#include <math.h>

#define C64   64
#define K2    9
#define HI    256
#define WI    256
#define HO    512
#define WO    512
#define NPIX  (HO*WO)          // 262144
#define PPB   64               // pixels per block
#define NTH   256              // 8 warps
#define H1S   68               // h1 row stride (floats): 17 x 16B, odd -> conflict-free LDS.128
#define H2S   260              // h2 row stride (floats): 65 x 16B, odd -> conflict-free LDS.128
#define XCS   65               // xc row stride (floats): odd -> conflict-free scalar LDS

typedef unsigned long long u64;

struct __align__(16) Smem {
    float pose[3][PPB];        //   768 B
    int   iy[PPB];             //   256 B
    int   ix[PPB];             //   256 B
    float red[8][PPB][3];      //  6144 B
    float h1[PPB][H1S];        // 17408 B
    float h2[PPB][H2S];        // 66560 B
    float xc[PPB][XCS];        // 16640 B
};                              // 108032 B total -> 2 blocks/SM

__device__ __forceinline__ u64 ffma2(u64 a, u64 b, u64 c) {
    u64 d;
    asm("fma.rn.f32x2 %0, %1, %2, %3;" : "=l"(d) : "l"(a), "l"(b), "l"(c));
    return d;
}
__device__ __forceinline__ float hadd2(u64 a) {
    float lo, hi;
    asm("mov.b64 {%0, %1}, %2;" : "=f"(lo), "=f"(hi) : "l"(a));
    return lo + hi;
}

// ---- layer 1: h1[p][o] = relu(W1[o,:3] @ pose[:,p] + b1[o]) ----
__device__ __forceinline__ void mlp_h1(Smem& s, const float* __restrict__ w1,
                                       const float* __restrict__ b1, int tid) {
    int o  = tid & 63;
    int pb = tid >> 6;              // 4 groups of 16 pixels
    float wa = __ldg(w1 + o * 3 + 0);
    float wb = __ldg(w1 + o * 3 + 1);
    float wc = __ldg(w1 + o * 3 + 2);
    float bb = __ldg(b1 + o);
    #pragma unroll 4
    for (int p = pb * 16; p < pb * 16 + 16; p++) {
        float v = fmaf(wa, s.pose[0][p],
                  fmaf(wb, s.pose[1][p],
                  fmaf(wc, s.pose[2][p], bb)));
        s.h1[p][o] = fmaxf(v, 0.f);
    }
}

// ---- layer 2: h2[p][o] = relu(W2[o,:64] @ h1[p,:] + b2[o]) ----
// warp -> 32 outputs (groups of 4), lane -> pixel pair (lane, lane+32)
__device__ __forceinline__ void mlp_h2(Smem& s, const float* __restrict__ w2,
                                       const float* __restrict__ b2,
                                       int warp, int lane) {
    const ulonglong2* h1a = reinterpret_cast<const ulonglong2*>(s.h1[lane]);
    const ulonglong2* h1b = reinterpret_cast<const ulonglong2*>(s.h1[lane + 32]);
    const int obase = warp * 32;

    for (int g = 0; g < 8; g++) {
        const int o = obase + g * 4;
        const ulonglong2* wr = reinterpret_cast<const ulonglong2*>(w2 + o * 64);
        u64 acc[4][2];
        #pragma unroll
        for (int oi = 0; oi < 4; oi++) { acc[oi][0] = 0ull; acc[oi][1] = 0ull; }

        #pragma unroll 2
        for (int k4 = 0; k4 < 16; k4++) {
            ulonglong2 ha = h1a[k4];
            ulonglong2 hb = h1b[k4];
            #pragma unroll
            for (int oi = 0; oi < 4; oi++) {
                ulonglong2 wv = wr[oi * 16 + k4];
                acc[oi][0] = ffma2(wv.x, ha.x, acc[oi][0]);
                acc[oi][0] = ffma2(wv.y, ha.y, acc[oi][0]);
                acc[oi][1] = ffma2(wv.x, hb.x, acc[oi][1]);
                acc[oi][1] = ffma2(wv.y, hb.y, acc[oi][1]);
            }
        }
        float4 r0, r1;
        float b0 = __ldg(b2 + o + 0), b1v = __ldg(b2 + o + 1);
        float b2v = __ldg(b2 + o + 2), b3v = __ldg(b2 + o + 3);
        r0.x = fmaxf(hadd2(acc[0][0]) + b0,  0.f);
        r0.y = fmaxf(hadd2(acc[1][0]) + b1v, 0.f);
        r0.z = fmaxf(hadd2(acc[2][0]) + b2v, 0.f);
        r0.w = fmaxf(hadd2(acc[3][0]) + b3v, 0.f);
        r1.x = fmaxf(hadd2(acc[0][1]) + b0,  0.f);
        r1.y = fmaxf(hadd2(acc[1][1]) + b1v, 0.f);
        r1.z = fmaxf(hadd2(acc[2][1]) + b2v, 0.f);
        r1.w = fmaxf(hadd2(acc[3][1]) + b3v, 0.f);
        *reinterpret_cast<float4*>(&s.h2[lane][o])      = r0;
        *reinterpret_cast<float4*>(&s.h2[lane + 32][o]) = r1;
    }
}

__global__ void __launch_bounds__(NTH, 2)
biupsampler_fused(const float* __restrict__ x,
                  const float* __restrict__ poseMap,
                  const int*   __restrict__ imY,
                  const int*   __restrict__ imX,
                  const float* __restrict__ sigmar,
                  const float* __restrict__ dw_w1, const float* __restrict__ dw_b1,
                  const float* __restrict__ dw_w2, const float* __restrict__ dw_b2,
                  const float* __restrict__ dw_w3, const float* __restrict__ dw_b3,
                  const float* __restrict__ pw_w1, const float* __restrict__ pw_b1,
                  const float* __restrict__ pw_w2, const float* __restrict__ pw_b2,
                  const float* __restrict__ pw_w3, const float* __restrict__ pw_b3,
                  float* __restrict__ out)
{
    extern __shared__ __align__(16) unsigned char smem_raw[];
    Smem& s = *reinterpret_cast<Smem*>(smem_raw);

    const int tid  = threadIdx.x;
    const int warp = tid >> 5;
    const int lane = tid & 31;
    const int pix0 = blockIdx.x * PPB;

    // ---- stage 0: load pose + gather maps ----
    for (int i = tid; i < 3 * PPB; i += NTH) {
        int j = i / PPB, p = i % PPB;
        s.pose[j][p] = __ldg(poseMap + j * NPIX + pix0 + p);
    }
    if (tid < PPB)           s.iy[tid]        = __ldg(imY + pix0 + tid);
    else if (tid < 2 * PPB)  s.ix[tid - PPB]  = __ldg(imX + pix0 + tid - PPB);
    __syncthreads();

    // ===================== DW branch =====================
    mlp_h1(s, dw_w1, dw_b1, tid);
    __syncthreads();
    mlp_h2(s, dw_w2, dw_b2, warp, lane);
    __syncthreads();

    // ---- pass 1: dw = W3 @ h2 (warp-uniform weights), gather, softmax -> xc ----
    {
        const ulonglong2* h2a = reinterpret_cast<const ulonglong2*>(s.h2[lane]);
        const ulonglong2* h2b = reinterpret_cast<const ulonglong2*>(s.h2[lane + 32]);
        const int pa = lane, pb = lane + 32;
        const int iya = s.iy[pa], ixa = s.ix[pa];
        const int iyb = s.iy[pb], ixb = s.ix[pb];

        for (int c8 = 0; c8 < 8; c8++) {
            const int c = warp * 8 + c8;
            const ulonglong2* wr = reinterpret_cast<const ulonglong2*>(dw_w3 + c * 9 * 256);

            u64 acc[9][2];
            #pragma unroll
            for (int t = 0; t < 9; t++) { acc[t][0] = 0ull; acc[t][1] = 0ull; }

            #pragma unroll 1
            for (int k4 = 0; k4 < 64; k4++) {
                ulonglong2 ha = h2a[k4];
                ulonglong2 hb = h2b[k4];
                #pragma unroll
                for (int t = 0; t < 9; t++) {
                    ulonglong2 wv = wr[t * 64 + k4];
                    acc[t][0] = ffma2(wv.x, ha.x, acc[t][0]);
                    acc[t][0] = ffma2(wv.y, ha.y, acc[t][0]);
                    acc[t][1] = ffma2(wv.x, hb.x, acc[t][1]);
                    acc[t][1] = ffma2(wv.y, hb.y, acc[t][1]);
                }
            }

            const float sg = __ldg(sigmar + c);
            const float* xplane = x + c * (HI * WI);
            const float* b3r = dw_b3 + c * 9;

            #pragma unroll
            for (int j = 0; j < 2; j++) {
                const int iy = j ? iyb : iya;
                const int ix = j ? ixb : ixa;

                float dwv[9], h[9];
                #pragma unroll
                for (int t = 0; t < 9; t++)
                    dwv[t] = hadd2(acc[t][j]) + __ldg(b3r + t);

                #pragma unroll
                for (int t = 0; t < 9; t++) {
                    int yy = iy + t / 3 - 1;
                    int xx = ix + t % 3 - 1;
                    bool ok = ((unsigned)yy < HI) && ((unsigned)xx < WI);
                    h[t] = ok ? __ldg(xplane + yy * WI + xx) : 0.f;
                }

                // softmax(dw) -> mean
                float m = dwv[0];
                #pragma unroll
                for (int t = 1; t < 9; t++) m = fmaxf(m, dwv[t]);
                float es = 0.f, hm = 0.f;
                #pragma unroll
                for (int t = 0; t < 9; t++) {
                    float e = __expf(dwv[t] - m);
                    es += e;
                    hm  = fmaf(h[t], e, hm);
                }
                float mean = hm / es;

                // bw = dw + sigmar*(h-mean)^2 ; softmax(bw)-weighted sum
                float bw[9], m2 = -3.4e38f;
                #pragma unroll
                for (int t = 0; t < 9; t++) {
                    float d = h[t] - mean;
                    bw[t] = fmaf(sg * d, d, dwv[t]);
                    m2 = fmaxf(m2, bw[t]);
                }
                float s2 = 0.f, xcv = 0.f;
                #pragma unroll
                for (int t = 0; t < 9; t++) {
                    float ee = __expf(bw[t] - m2);
                    s2  += ee;
                    xcv  = fmaf(h[t], ee, xcv);
                }
                s.xc[j ? pb : pa][c] = xcv / s2;
            }
        }
    }
    __syncthreads();

    // ===================== PW branch =====================
    mlp_h1(s, pw_w1, pw_b1, tid);
    __syncthreads();
    mlp_h2(s, pw_w2, pw_b2, warp, lane);
    __syncthreads();

    // ---- pass 2: pw = PW3 @ h2 (warp-uniform weights), contract with xc ----
    {
        const ulonglong2* h2a = reinterpret_cast<const ulonglong2*>(s.h2[lane]);
        const ulonglong2* h2b = reinterpret_cast<const ulonglong2*>(s.h2[lane + 32]);

        float o_[3][2];
        #pragma unroll
        for (int r = 0; r < 3; r++) { o_[r][0] = 0.f; o_[r][1] = 0.f; }

        for (int c8 = 0; c8 < 8; c8++) {
            const int c = warp * 8 + c8;
            const ulonglong2* wr = reinterpret_cast<const ulonglong2*>(pw_w3 + c * 3 * 256);

            u64 acc[3][2];
            #pragma unroll
            for (int r = 0; r < 3; r++) { acc[r][0] = 0ull; acc[r][1] = 0ull; }

            #pragma unroll 1
            for (int k4 = 0; k4 < 64; k4++) {
                ulonglong2 ha = h2a[k4];
                ulonglong2 hb = h2b[k4];
                #pragma unroll
                for (int r = 0; r < 3; r++) {
                    ulonglong2 wv = wr[r * 64 + k4];
                    acc[r][0] = ffma2(wv.x, ha.x, acc[r][0]);
                    acc[r][0] = ffma2(wv.y, ha.y, acc[r][0]);
                    acc[r][1] = ffma2(wv.x, hb.x, acc[r][1]);
                    acc[r][1] = ffma2(wv.y, hb.y, acc[r][1]);
                }
            }

            const float xca = s.xc[lane][c];
            const float xcb = s.xc[lane + 32][c];
            #pragma unroll
            for (int r = 0; r < 3; r++) {
                float b = __ldg(pw_b3 + c * 3 + r);
                o_[r][0] = fmaf(xca, hadd2(acc[r][0]) + b, o_[r][0]);
                o_[r][1] = fmaf(xcb, hadd2(acc[r][1]) + b, o_[r][1]);
            }
        }

        #pragma unroll
        for (int r = 0; r < 3; r++) {
            s.red[warp][lane][r]      = o_[r][0];
            s.red[warp][lane + 32][r] = o_[r][1];
        }
    }
    __syncthreads();

    // ---- cross-warp channel reduction + output ----
    if (tid < PPB) {
        const int p = tid;
        #pragma unroll
        for (int r = 0; r < 3; r++) {
            float v = 0.f;
            #pragma unroll
            for (int w = 0; w < 8; w++) v += s.red[w][p][r];
            out[r * NPIX + pix0 + p] = v;
        }
    }
}

extern "C" void kernel_launch(void* const* d_in, const int* in_sizes, int n_in,
                              void* d_out, int out_size) {
    (void)in_sizes; (void)n_in; (void)out_size;
    const float* x      = (const float*)d_in[0];
    const float* pose   = (const float*)d_in[1];
    const int*   imY    = (const int*)  d_in[2];
    const int*   imX    = (const int*)  d_in[3];
    const float* sigmar = (const float*)d_in[4];
    const float* dw_w1  = (const float*)d_in[5];
    const float* dw_b1  = (const float*)d_in[6];
    const float* dw_w2  = (const float*)d_in[7];
    const float* dw_b2  = (const float*)d_in[8];
    const float* dw_w3  = (const float*)d_in[9];
    const float* dw_b3  = (const float*)d_in[10];
    const float* pw_w1  = (const float*)d_in[11];
    const float* pw_b1  = (const float*)d_in[12];
    const float* pw_w2  = (const float*)d_in[13];
    const float* pw_b2  = (const float*)d_in[14];
    const float* pw_w3  = (const float*)d_in[15];
    const float* pw_b3  = (const float*)d_in[16];
    float* out = (float*)d_out;

    const int smem = (int)sizeof(Smem);
    cudaFuncSetAttribute(biupsampler_fused,
                         cudaFuncAttributeMaxDynamicSharedMemorySize, smem);

    biupsampler_fused<<<NPIX / PPB, NTH, smem>>>(
        x, pose, imY, imX, sigmar,
        dw_w1, dw_b1, dw_w2, dw_b2, dw_w3, dw_b3,
        pw_w1, pw_b1, pw_w2, pw_b2, pw_w3, pw_b3,
        out);
}

// round 4
// speedup vs baseline: 4.7925x; 1.4422x over previous
#include <cuda_runtime.h>
#include <math.h>

#define HI    256
#define WI    256
#define NPIX  262144
#define PPB   128              // pixels per block
#define NTH   512              // 16 warps
#define H1S   68               // h1 row stride (floats), px-major
#define H2TS  130              // h2t row stride (floats), k-major, even -> 8B-aligned cols
#define XCS   65

typedef unsigned long long u64;

struct __align__(16) Smem {
    float pose[3][PPB];        //  1536 B
    int   iy[PPB];             //   512 B
    int   ix[PPB];             //   512 B
    float xc[PPB][XCS];        // 33280 B
    union {
        float h1[PPB][H1S];    // 34816 B
        float red[16][PPB][3]; // 24576 B
    } u;
    float h2t[256][H2TS];      // 133120 B
};                              // 203776 B total

__device__ __forceinline__ u64 ffma2(u64 a, u64 b, u64 c) {
    u64 d; asm("fma.rn.f32x2 %0,%1,%2,%3;" : "=l"(d) : "l"(a), "l"(b), "l"(c)); return d;
}
__device__ __forceinline__ u64 add2(u64 a, u64 b) {
    u64 d; asm("add.rn.f32x2 %0,%1,%2;" : "=l"(d) : "l"(a), "l"(b)); return d;
}
__device__ __forceinline__ u64 dup2(float f) {
    u64 d; asm("mov.b64 %0,{%1,%1};" : "=l"(d) : "f"(f)); return d;
}
__device__ __forceinline__ u64 pack2(float x, float y) {
    u64 d; asm("mov.b64 %0,{%1,%2};" : "=l"(d) : "f"(x), "f"(y)); return d;
}
__device__ __forceinline__ float2 unpk(u64 a) {
    float2 r; asm("mov.b64 {%0,%1},%2;" : "=f"(r.x), "=f"(r.y) : "l"(a)); return r;
}
__device__ __forceinline__ float hadd2(u64 a) { float2 r = unpk(a); return r.x + r.y; }

// ---- layer 1: h1[p][o] = relu(W1[o,:3] @ pose[:,p] + b1[o]) ----
__device__ __forceinline__ void mlp_h1(Smem& s, const float* __restrict__ w1,
                                       const float* __restrict__ b1, int tid) {
    int o  = tid & 63;
    int pb = tid >> 6;              // 8 groups of 16 pixels
    float wa = __ldg(w1 + o * 3 + 0);
    float wb = __ldg(w1 + o * 3 + 1);
    float wc = __ldg(w1 + o * 3 + 2);
    float bb = __ldg(b1 + o);
    #pragma unroll 4
    for (int p = pb * 16; p < pb * 16 + 16; p++) {
        float v = fmaf(wa, s.pose[0][p],
                  fmaf(wb, s.pose[1][p],
                  fmaf(wc, s.pose[2][p], bb)));
        s.u.h1[p][o] = fmaxf(v, 0.f);
    }
}

// ---- layer 2: h2t[o][p] = relu(W2[o,:64] @ h1[p,:] + b2[o]) ----
// warp -> 16 outputs, lane -> pixels {l, l+32, l+64, l+96}; k-pair packing
__device__ __forceinline__ void mlp_h2(Smem& s, const float* __restrict__ w2,
                                       const float* __restrict__ b2,
                                       int warp, int lane) {
    const ulonglong2* ha = reinterpret_cast<const ulonglong2*>(s.u.h1[lane]);
    const ulonglong2* hb = reinterpret_cast<const ulonglong2*>(s.u.h1[lane + 32]);
    const ulonglong2* hc = reinterpret_cast<const ulonglong2*>(s.u.h1[lane + 64]);
    const ulonglong2* hd = reinterpret_cast<const ulonglong2*>(s.u.h1[lane + 96]);
    const int obase = warp * 16;

    #pragma unroll 1
    for (int g = 0; g < 4; g++) {
        const int o = obase + g * 4;
        const ulonglong2* wr = reinterpret_cast<const ulonglong2*>(w2 + o * 64);
        u64 acc[4][4];
        #pragma unroll
        for (int oi = 0; oi < 4; oi++)
            #pragma unroll
            for (int j = 0; j < 4; j++) acc[oi][j] = 0ull;

        #pragma unroll 2
        for (int k4 = 0; k4 < 16; k4++) {
            ulonglong2 va = ha[k4], vb = hb[k4], vc = hc[k4], vd = hd[k4];
            #pragma unroll
            for (int oi = 0; oi < 4; oi++) {
                ulonglong2 wv = wr[oi * 16 + k4];
                acc[oi][0] = ffma2(wv.x, va.x, acc[oi][0]);
                acc[oi][0] = ffma2(wv.y, va.y, acc[oi][0]);
                acc[oi][1] = ffma2(wv.x, vb.x, acc[oi][1]);
                acc[oi][1] = ffma2(wv.y, vb.y, acc[oi][1]);
                acc[oi][2] = ffma2(wv.x, vc.x, acc[oi][2]);
                acc[oi][2] = ffma2(wv.y, vc.y, acc[oi][2]);
                acc[oi][3] = ffma2(wv.x, vd.x, acc[oi][3]);
                acc[oi][3] = ffma2(wv.y, vd.y, acc[oi][3]);
            }
        }
        #pragma unroll
        for (int oi = 0; oi < 4; oi++) {
            float b = __ldg(b2 + o + oi);
            s.h2t[o + oi][lane]      = fmaxf(hadd2(acc[oi][0]) + b, 0.f);
            s.h2t[o + oi][lane + 32] = fmaxf(hadd2(acc[oi][1]) + b, 0.f);
            s.h2t[o + oi][lane + 64] = fmaxf(hadd2(acc[oi][2]) + b, 0.f);
            s.h2t[o + oi][lane + 96] = fmaxf(hadd2(acc[oi][3]) + b, 0.f);
        }
    }
}

// ---- per-pixel gather + double softmax tail ----
__device__ __forceinline__ float pixel_tail(const float* dwv, const float* __restrict__ xplane,
                                            int iy, int ix, float sg) {
    float h[9];
    #pragma unroll
    for (int t = 0; t < 9; t++) {
        int yy = iy + t / 3 - 1;
        int xx = ix + t % 3 - 1;
        bool ok = ((unsigned)yy < HI) && ((unsigned)xx < WI);
        h[t] = ok ? __ldg(xplane + yy * WI + xx) : 0.f;
    }
    float m = dwv[0];
    #pragma unroll
    for (int t = 1; t < 9; t++) m = fmaxf(m, dwv[t]);
    float es = 0.f, hm = 0.f;
    #pragma unroll
    for (int t = 0; t < 9; t++) {
        float e = __expf(dwv[t] - m);
        es += e;
        hm  = fmaf(h[t], e, hm);
    }
    float mean = hm / es;

    float bw[9], m2 = -3.4e38f;
    #pragma unroll
    for (int t = 0; t < 9; t++) {
        float d = h[t] - mean;
        bw[t] = fmaf(sg * d, d, dwv[t]);
        m2 = fmaxf(m2, bw[t]);
    }
    float s2 = 0.f, xcv = 0.f;
    #pragma unroll
    for (int t = 0; t < 9; t++) {
        float ee = __expf(bw[t] - m2);
        s2  += ee;
        xcv  = fmaf(h[t], ee, xcv);
    }
    return xcv / s2;
}

__global__ void __launch_bounds__(NTH, 1)
biupsampler_fused(const float* __restrict__ x,
                  const float* __restrict__ poseMap,
                  const int*   __restrict__ imY,
                  const int*   __restrict__ imX,
                  const float* __restrict__ sigmar,
                  const float* __restrict__ dw_w1, const float* __restrict__ dw_b1,
                  const float* __restrict__ dw_w2, const float* __restrict__ dw_b2,
                  const float* __restrict__ dw_w3, const float* __restrict__ dw_b3,
                  const float* __restrict__ pw_w1, const float* __restrict__ pw_b1,
                  const float* __restrict__ pw_w2, const float* __restrict__ pw_b2,
                  const float* __restrict__ pw_w3, const float* __restrict__ pw_b3,
                  float* __restrict__ out)
{
    extern __shared__ __align__(16) unsigned char smem_raw[];
    Smem& s = *reinterpret_cast<Smem*>(smem_raw);

    const int tid  = threadIdx.x;
    const int warp = tid >> 5;
    const int lane = tid & 31;
    const int pix0 = blockIdx.x * PPB;
    const int col  = 2 * lane;     // pair A: col,col+1 ; pair B: col+64,col+65

    // ---- stage 0 ----
    if (tid < 3 * PPB) {
        int j = tid >> 7, p = tid & 127;
        s.pose[j][p] = __ldg(poseMap + j * NPIX + pix0 + p);
    }
    if (tid < PPB)           s.iy[tid]       = __ldg(imY + pix0 + tid);
    else if (tid < 2 * PPB)  s.ix[tid - PPB] = __ldg(imX + pix0 + tid - PPB);
    __syncthreads();

    // ===================== DW branch =====================
    mlp_h1(s, dw_w1, dw_b1, tid);
    __syncthreads();
    mlp_h2(s, dw_w2, dw_b2, warp, lane);
    __syncthreads();

    // ---- pass 1: dw = W3 @ h2 (pixel-pair packed), gather+softmax -> xc ----
    {
        const int iyA0 = s.iy[col],      ixA0 = s.ix[col];
        const int iyA1 = s.iy[col + 1],  ixA1 = s.ix[col + 1];
        const int iyB0 = s.iy[col + 64], ixB0 = s.ix[col + 64];
        const int iyB1 = s.iy[col + 65], ixB1 = s.ix[col + 65];

        #pragma unroll 1
        for (int c4 = 0; c4 < 4; c4++) {
            const int c = warp * 4 + c4;
            const float4* wr = reinterpret_cast<const float4*>(dw_w3 + c * 9 * 256);

            u64 acc[9][2];
            #pragma unroll
            for (int t = 0; t < 9; t++) { acc[t][0] = 0ull; acc[t][1] = 0ull; }

            #pragma unroll 1
            for (int k4 = 0; k4 < 64; k4++) {
                const int k = k4 * 4;
                u64 hA0 = *(const u64*)&s.h2t[k + 0][col];
                u64 hA1 = *(const u64*)&s.h2t[k + 1][col];
                u64 hA2 = *(const u64*)&s.h2t[k + 2][col];
                u64 hA3 = *(const u64*)&s.h2t[k + 3][col];
                u64 hB0 = *(const u64*)&s.h2t[k + 0][col + 64];
                u64 hB1 = *(const u64*)&s.h2t[k + 1][col + 64];
                u64 hB2 = *(const u64*)&s.h2t[k + 2][col + 64];
                u64 hB3 = *(const u64*)&s.h2t[k + 3][col + 64];
                #pragma unroll
                for (int t = 0; t < 9; t++) {
                    float4 w = __ldg(wr + t * 64 + k4);
                    u64 w0 = dup2(w.x), w1 = dup2(w.y), w2 = dup2(w.z), w3 = dup2(w.w);
                    acc[t][0] = ffma2(w0, hA0, acc[t][0]);
                    acc[t][0] = ffma2(w1, hA1, acc[t][0]);
                    acc[t][0] = ffma2(w2, hA2, acc[t][0]);
                    acc[t][0] = ffma2(w3, hA3, acc[t][0]);
                    acc[t][1] = ffma2(w0, hB0, acc[t][1]);
                    acc[t][1] = ffma2(w1, hB1, acc[t][1]);
                    acc[t][1] = ffma2(w2, hB2, acc[t][1]);
                    acc[t][1] = ffma2(w3, hB3, acc[t][1]);
                }
            }

            const float sg = __ldg(sigmar + c);
            const float* xplane = x + c * (HI * WI);
            const float* b3r = dw_b3 + c * 9;

            float dA0[9], dA1[9], dB0[9], dB1[9];
            #pragma unroll
            for (int t = 0; t < 9; t++) {
                float b = __ldg(b3r + t);
                float2 a = unpk(acc[t][0]);
                float2 bb = unpk(acc[t][1]);
                dA0[t] = a.x + b;  dA1[t] = a.y + b;
                dB0[t] = bb.x + b; dB1[t] = bb.y + b;
            }
            s.xc[col][c]      = pixel_tail(dA0, xplane, iyA0, ixA0, sg);
            s.xc[col + 1][c]  = pixel_tail(dA1, xplane, iyA1, ixA1, sg);
            s.xc[col + 64][c] = pixel_tail(dB0, xplane, iyB0, ixB0, sg);
            s.xc[col + 65][c] = pixel_tail(dB1, xplane, iyB1, ixB1, sg);
        }
    }
    __syncthreads();

    // ===================== PW branch =====================
    mlp_h1(s, pw_w1, pw_b1, tid);
    __syncthreads();
    mlp_h2(s, pw_w2, pw_b2, warp, lane);
    __syncthreads();

    // ---- pass 2: pw = PW3 @ h2, contract with xc (pixel-pair packed) ----
    {
        u64 oA[3] = {0ull, 0ull, 0ull};
        u64 oB[3] = {0ull, 0ull, 0ull};

        #pragma unroll 1
        for (int c4 = 0; c4 < 4; c4++) {
            const int c = warp * 4 + c4;
            const float4* wr = reinterpret_cast<const float4*>(pw_w3 + c * 3 * 256);

            u64 acc[3][2];
            #pragma unroll
            for (int r = 0; r < 3; r++) { acc[r][0] = 0ull; acc[r][1] = 0ull; }

            #pragma unroll 1
            for (int k4 = 0; k4 < 64; k4++) {
                const int k = k4 * 4;
                u64 hA0 = *(const u64*)&s.h2t[k + 0][col];
                u64 hA1 = *(const u64*)&s.h2t[k + 1][col];
                u64 hA2 = *(const u64*)&s.h2t[k + 2][col];
                u64 hA3 = *(const u64*)&s.h2t[k + 3][col];
                u64 hB0 = *(const u64*)&s.h2t[k + 0][col + 64];
                u64 hB1 = *(const u64*)&s.h2t[k + 1][col + 64];
                u64 hB2 = *(const u64*)&s.h2t[k + 2][col + 64];
                u64 hB3 = *(const u64*)&s.h2t[k + 3][col + 64];
                #pragma unroll
                for (int r = 0; r < 3; r++) {
                    float4 w = __ldg(wr + r * 64 + k4);
                    u64 w0 = dup2(w.x), w1 = dup2(w.y), w2 = dup2(w.z), w3 = dup2(w.w);
                    acc[r][0] = ffma2(w0, hA0, acc[r][0]);
                    acc[r][0] = ffma2(w1, hA1, acc[r][0]);
                    acc[r][0] = ffma2(w2, hA2, acc[r][0]);
                    acc[r][0] = ffma2(w3, hA3, acc[r][0]);
                    acc[r][1] = ffma2(w0, hB0, acc[r][1]);
                    acc[r][1] = ffma2(w1, hB1, acc[r][1]);
                    acc[r][1] = ffma2(w2, hB2, acc[r][1]);
                    acc[r][1] = ffma2(w3, hB3, acc[r][1]);
                }
            }

            u64 xA = pack2(s.xc[col][c],      s.xc[col + 1][c]);
            u64 xB = pack2(s.xc[col + 64][c], s.xc[col + 65][c]);
            #pragma unroll
            for (int r = 0; r < 3; r++) {
                u64 b2v = dup2(__ldg(pw_b3 + c * 3 + r));
                oA[r] = ffma2(xA, add2(acc[r][0], b2v), oA[r]);
                oB[r] = ffma2(xB, add2(acc[r][1], b2v), oB[r]);
            }
        }

        #pragma unroll
        for (int r = 0; r < 3; r++) {
            float2 a = unpk(oA[r]);
            float2 b = unpk(oB[r]);
            s.u.red[warp][col][r]      = a.x;
            s.u.red[warp][col + 1][r]  = a.y;
            s.u.red[warp][col + 64][r] = b.x;
            s.u.red[warp][col + 65][r] = b.y;
        }
    }
    __syncthreads();

    // ---- cross-warp channel reduction + output ----
    {
        const int p = tid >> 2;
        const int r = tid & 3;
        if (r < 3) {
            float v = 0.f;
            #pragma unroll
            for (int w = 0; w < 16; w++) v += s.u.red[w][p][r];
            out[r * NPIX + pix0 + p] = v;
        }
    }
}

extern "C" void kernel_launch(void* const* d_in, const int* in_sizes, int n_in,
                              void* d_out, int out_size) {
    (void)in_sizes; (void)n_in; (void)out_size;
    const float* x      = (const float*)d_in[0];
    const float* pose   = (const float*)d_in[1];
    const int*   imY    = (const int*)  d_in[2];
    const int*   imX    = (const int*)  d_in[3];
    const float* sigmar = (const float*)d_in[4];
    const float* dw_w1  = (const float*)d_in[5];
    const float* dw_b1  = (const float*)d_in[6];
    const float* dw_w2  = (const float*)d_in[7];
    const float* dw_b2  = (const float*)d_in[8];
    const float* dw_w3  = (const float*)d_in[9];
    const float* dw_b3  = (const float*)d_in[10];
    const float* pw_w1  = (const float*)d_in[11];
    const float* pw_b1  = (const float*)d_in[12];
    const float* pw_w2  = (const float*)d_in[13];
    const float* pw_b2  = (const float*)d_in[14];
    const float* pw_w3  = (const float*)d_in[15];
    const float* pw_b3  = (const float*)d_in[16];
    float* out = (float*)d_out;

    const int smem = (int)sizeof(Smem);
    cudaFuncSetAttribute(biupsampler_fused,
                         cudaFuncAttributeMaxDynamicSharedMemorySize, smem);

    biupsampler_fused<<<NPIX / PPB, NTH, smem>>>(
        x, pose, imY, imX, sigmar,
        dw_w1, dw_b1, dw_w2, dw_b2, dw_w3, dw_b3,
        pw_w1, pw_b1, pw_w2, pw_b2, pw_w3, pw_b3,
        out);
}

// round 5
// speedup vs baseline: 4.9115x; 1.0248x over previous
#include <cuda_runtime.h>
#include <math.h>

#define HI    256
#define WI    256
#define NPIX  262144
#define PPB   128              // pixels per block
#define NTH   512              // 16 warps
#define H1S   68               // h1 row stride (floats), px-major
#define H2TS  130              // h2t row stride (floats), k-major
#define XCS   65

typedef unsigned long long u64;

__device__ float g_xt[HI * WI * 64];   // x transposed to [y][x][c], 16 MB

struct __align__(16) Smem {
    float pose[3][PPB];        //  1536 B
    int   iy[PPB];             //   512 B
    int   ix[PPB];             //   512 B
    float xc[PPB][XCS];        // 33280 B
    union {
        float h1[PPB][H1S];    // 34816 B
        float red[16][PPB][3]; // 24576 B
        u64   dws[16][17][9];  // 19584 B  [px-pair][c+pad][tap], f32x2 (even,odd px)
    } u;
    float h2t[256][H2TS];      // 133120 B
};                              // 203776 B total

__device__ __forceinline__ u64 ffma2(u64 a, u64 b, u64 c) {
    u64 d; asm("fma.rn.f32x2 %0,%1,%2,%3;" : "=l"(d) : "l"(a), "l"(b), "l"(c)); return d;
}
__device__ __forceinline__ u64 add2(u64 a, u64 b) {
    u64 d; asm("add.rn.f32x2 %0,%1,%2;" : "=l"(d) : "l"(a), "l"(b)); return d;
}
__device__ __forceinline__ u64 dup2(float f) {
    u64 d; asm("mov.b64 %0,{%1,%1};" : "=l"(d) : "f"(f)); return d;
}
__device__ __forceinline__ u64 pack2(float x, float y) {
    u64 d; asm("mov.b64 %0,{%1,%2};" : "=l"(d) : "f"(x), "f"(y)); return d;
}
__device__ __forceinline__ float2 unpk(u64 a) {
    float2 r; asm("mov.b64 {%0,%1},%2;" : "=f"(r.x), "=f"(r.y) : "l"(a)); return r;
}
__device__ __forceinline__ float hadd2(u64 a) { float2 r = unpk(a); return r.x + r.y; }

// ======== prep: x[64][256][256] -> g_xt[y][x][64] ========
__global__ void __launch_bounds__(256)
transpose_x_kernel(const float* __restrict__ x) {
    extern __shared__ float tile[];   // [64][257]
    const int y   = blockIdx.x;
    const int tid = threadIdx.x;
    for (int i = tid; i < 64 * 256; i += 256) {
        int c = i >> 8, xx = i & 255;
        tile[c * 257 + xx] = __ldg(x + c * 65536 + y * 256 + xx);
    }
    __syncthreads();
    for (int i = tid; i < 64 * 256; i += 256) {
        int xx = i >> 6, c = i & 63;
        g_xt[(y * 256 + xx) * 64 + c] = tile[c * 257 + xx];
    }
}

// ---- layer 1 ----
__device__ __forceinline__ void mlp_h1(Smem& s, const float* __restrict__ w1,
                                       const float* __restrict__ b1, int tid) {
    int o  = tid & 63;
    int pb = tid >> 6;
    float wa = __ldg(w1 + o * 3 + 0);
    float wb = __ldg(w1 + o * 3 + 1);
    float wc = __ldg(w1 + o * 3 + 2);
    float bb = __ldg(b1 + o);
    #pragma unroll 4
    for (int p = pb * 16; p < pb * 16 + 16; p++) {
        float v = fmaf(wa, s.pose[0][p],
                  fmaf(wb, s.pose[1][p],
                  fmaf(wc, s.pose[2][p], bb)));
        s.u.h1[p][o] = fmaxf(v, 0.f);
    }
}

// ---- layer 2: h2t[o][p] = relu(W2 @ h1 + b2), k-major output ----
__device__ __forceinline__ void mlp_h2(Smem& s, const float* __restrict__ w2,
                                       const float* __restrict__ b2,
                                       int warp, int lane) {
    const ulonglong2* ha = reinterpret_cast<const ulonglong2*>(s.u.h1[lane]);
    const ulonglong2* hb = reinterpret_cast<const ulonglong2*>(s.u.h1[lane + 32]);
    const ulonglong2* hc = reinterpret_cast<const ulonglong2*>(s.u.h1[lane + 64]);
    const ulonglong2* hd = reinterpret_cast<const ulonglong2*>(s.u.h1[lane + 96]);
    const int obase = warp * 16;

    #pragma unroll 1
    for (int g = 0; g < 4; g++) {
        const int o = obase + g * 4;
        const ulonglong2* wr = reinterpret_cast<const ulonglong2*>(w2 + o * 64);
        u64 acc[4][4];
        #pragma unroll
        for (int oi = 0; oi < 4; oi++)
            #pragma unroll
            for (int j = 0; j < 4; j++) acc[oi][j] = 0ull;

        #pragma unroll 2
        for (int k4 = 0; k4 < 16; k4++) {
            ulonglong2 va = ha[k4], vb = hb[k4], vc = hc[k4], vd = hd[k4];
            #pragma unroll
            for (int oi = 0; oi < 4; oi++) {
                ulonglong2 wv = wr[oi * 16 + k4];
                acc[oi][0] = ffma2(wv.x, va.x, acc[oi][0]);
                acc[oi][0] = ffma2(wv.y, va.y, acc[oi][0]);
                acc[oi][1] = ffma2(wv.x, vb.x, acc[oi][1]);
                acc[oi][1] = ffma2(wv.y, vb.y, acc[oi][1]);
                acc[oi][2] = ffma2(wv.x, vc.x, acc[oi][2]);
                acc[oi][2] = ffma2(wv.y, vc.y, acc[oi][2]);
                acc[oi][3] = ffma2(wv.x, vd.x, acc[oi][3]);
                acc[oi][3] = ffma2(wv.y, vd.y, acc[oi][3]);
            }
        }
        #pragma unroll
        for (int oi = 0; oi < 4; oi++) {
            float b = __ldg(b2 + o + oi);
            s.h2t[o + oi][lane]      = fmaxf(hadd2(acc[oi][0]) + b, 0.f);
            s.h2t[o + oi][lane + 32] = fmaxf(hadd2(acc[oi][1]) + b, 0.f);
            s.h2t[o + oi][lane + 64] = fmaxf(hadd2(acc[oi][2]) + b, 0.f);
            s.h2t[o + oi][lane + 96] = fmaxf(hadd2(acc[oi][3]) + b, 0.f);
        }
    }
}

// ---- per-(px,c) double-softmax tail ----
__device__ __forceinline__ float pixel_tail2(const float* dwv, const float* h, float sg) {
    float m = dwv[0];
    #pragma unroll
    for (int t = 1; t < 9; t++) m = fmaxf(m, dwv[t]);
    float es = 0.f, hm = 0.f;
    #pragma unroll
    for (int t = 0; t < 9; t++) {
        float e = __expf(dwv[t] - m);
        es += e;
        hm  = fmaf(h[t], e, hm);
    }
    float mean = hm / es;

    float bw[9], m2 = -3.4e38f;
    #pragma unroll
    for (int t = 0; t < 9; t++) {
        float d = h[t] - mean;
        bw[t] = fmaf(sg * d, d, dwv[t]);
        m2 = fmaxf(m2, bw[t]);
    }
    float s2 = 0.f, xcv = 0.f;
    #pragma unroll
    for (int t = 0; t < 9; t++) {
        float ee = __expf(bw[t] - m2);
        s2  += ee;
        xcv  = fmaf(h[t], ee, xcv);
    }
    return xcv / s2;
}

__global__ void __launch_bounds__(NTH, 1)
biupsampler_fused(const float* __restrict__ x,
                  const float* __restrict__ poseMap,
                  const int*   __restrict__ imY,
                  const int*   __restrict__ imX,
                  const float* __restrict__ sigmar,
                  const float* __restrict__ dw_w1, const float* __restrict__ dw_b1,
                  const float* __restrict__ dw_w2, const float* __restrict__ dw_b2,
                  const float* __restrict__ dw_w3, const float* __restrict__ dw_b3,
                  const float* __restrict__ pw_w1, const float* __restrict__ pw_b1,
                  const float* __restrict__ pw_w2, const float* __restrict__ pw_b2,
                  const float* __restrict__ pw_w3, const float* __restrict__ pw_b3,
                  float* __restrict__ out)
{
    extern __shared__ __align__(16) unsigned char smem_raw[];
    Smem& s = *reinterpret_cast<Smem*>(smem_raw);

    const int tid  = threadIdx.x;
    const int warp = tid >> 5;
    const int lane = tid & 31;
    const int pix0 = blockIdx.x * PPB;
    const int col  = 2 * lane;     // pair A: col,col+1 ; pair B: col+64,col+65

    // ---- stage 0 ----
    if (tid < 3 * PPB) {
        int j = tid >> 7, p = tid & 127;
        s.pose[j][p] = __ldg(poseMap + j * NPIX + pix0 + p);
    }
    if (tid < PPB)           s.iy[tid]       = __ldg(imY + pix0 + tid);
    else if (tid < 2 * PPB)  s.ix[tid - PPB] = __ldg(imX + pix0 + tid - PPB);
    __syncthreads();

    // ===================== DW branch =====================
    mlp_h1(s, dw_w1, dw_b1, tid);
    __syncthreads();
    mlp_h2(s, dw_w2, dw_b2, warp, lane);
    __syncthreads();

    // ---- pass 1: GEMM (px-lane) -> stage dw -> coalesced gather tail (c-lane) ----
    #pragma unroll 1
    for (int c4 = 0; c4 < 4; c4++) {
        const int c = c4 * 16 + warp;               // 16 consecutive c across warps
        const float4* wr = reinterpret_cast<const float4*>(dw_w3 + c * 9 * 256);

        u64 acc[9][2];
        #pragma unroll
        for (int t = 0; t < 9; t++) { acc[t][0] = 0ull; acc[t][1] = 0ull; }

        #pragma unroll 1
        for (int k4 = 0; k4 < 64; k4++) {
            const int k = k4 * 4;
            u64 hA0 = *(const u64*)&s.h2t[k + 0][col];
            u64 hA1 = *(const u64*)&s.h2t[k + 1][col];
            u64 hA2 = *(const u64*)&s.h2t[k + 2][col];
            u64 hA3 = *(const u64*)&s.h2t[k + 3][col];
            u64 hB0 = *(const u64*)&s.h2t[k + 0][col + 64];
            u64 hB1 = *(const u64*)&s.h2t[k + 1][col + 64];
            u64 hB2 = *(const u64*)&s.h2t[k + 2][col + 64];
            u64 hB3 = *(const u64*)&s.h2t[k + 3][col + 64];
            #pragma unroll
            for (int t = 0; t < 9; t++) {
                float4 w = __ldg(wr + t * 64 + k4);
                u64 w0 = dup2(w.x), w1 = dup2(w.y), w2 = dup2(w.z), w3 = dup2(w.w);
                acc[t][0] = ffma2(w0, hA0, acc[t][0]);
                acc[t][0] = ffma2(w1, hA1, acc[t][0]);
                acc[t][0] = ffma2(w2, hA2, acc[t][0]);
                acc[t][0] = ffma2(w3, hA3, acc[t][0]);
                acc[t][1] = ffma2(w0, hB0, acc[t][1]);
                acc[t][1] = ffma2(w1, hB1, acc[t][1]);
                acc[t][1] = ffma2(w2, hB2, acc[t][1]);
                acc[t][1] = ffma2(w3, hB3, acc[t][1]);
            }
        }

        // bias, keep packed: acc[t][0] = px pair (col,col+1), acc[t][1] = (col+64,col+65)
        #pragma unroll
        for (int t = 0; t < 9; t++) {
            u64 bv = dup2(__ldg(dw_b3 + c * 9 + t));
            acc[t][0] = add2(acc[t][0], bv);
            acc[t][1] = add2(acc[t][1], bv);
        }

        // 4 pixel-chunks of 32: stage dw, then 1 thread = 1 (px, c) tail task
        #pragma unroll 1
        for (int j = 0; j < 4; j++) {
            __syncthreads();   // previous chunk's readers done before overwrite
            if ((lane >> 4) == (j & 1)) {
                const int pairIdx = lane & 15;       // px pair (32j + 2*pairIdx)
                const int sel = (j >> 1);            // 0 -> pair A, 1 -> pair B
                u64* dst = &s.u.dws[pairIdx][warp][0];
                #pragma unroll
                for (int t = 0; t < 9; t++) dst[t] = acc[t][sel];
            }
            __syncthreads();

            // tail task: px = 32j + tid/16, c_t = 16*c4 + (tid%16)
            const int pxo  = tid >> 4;               // 0..31
            const int px   = j * 32 + pxo;
            const int cw   = tid & 15;
            const int c_t  = c4 * 16 + cw;
            const int pair = pxo >> 1, par = pxo & 1;

            const float* dwsf = reinterpret_cast<const float*>(&s.u.dws[pair][cw][0]);
            float dwv[9];
            #pragma unroll
            for (int t = 0; t < 9; t++) dwv[t] = dwsf[2 * t + par];

            const int iy = s.iy[px], ix = s.ix[px];
            const float sg = __ldg(sigmar + c_t);

            float h[9];
            #pragma unroll
            for (int t = 0; t < 9; t++) {
                int yy = iy + t / 3 - 1;
                int xx = ix + t % 3 - 1;
                bool ok = ((unsigned)yy < HI) && ((unsigned)xx < WI);
                h[t] = ok ? __ldg(&g_xt[(yy * WI + xx) * 64 + c_t]) : 0.f;
            }

            s.xc[px][c_t] = pixel_tail2(dwv, h, sg);
        }
    }
    __syncthreads();

    // ===================== PW branch =====================
    mlp_h1(s, pw_w1, pw_b1, tid);
    __syncthreads();
    mlp_h2(s, pw_w2, pw_b2, warp, lane);
    __syncthreads();

    // ---- pass 2: pw = PW3 @ h2, contract with xc (pixel-pair packed) ----
    {
        u64 oA[3] = {0ull, 0ull, 0ull};
        u64 oB[3] = {0ull, 0ull, 0ull};

        #pragma unroll 1
        for (int c4 = 0; c4 < 4; c4++) {
            const int c = warp * 4 + c4;
            const float4* wr = reinterpret_cast<const float4*>(pw_w3 + c * 3 * 256);

            u64 acc[3][2];
            #pragma unroll
            for (int r = 0; r < 3; r++) { acc[r][0] = 0ull; acc[r][1] = 0ull; }

            #pragma unroll 1
            for (int k4 = 0; k4 < 64; k4++) {
                const int k = k4 * 4;
                u64 hA0 = *(const u64*)&s.h2t[k + 0][col];
                u64 hA1 = *(const u64*)&s.h2t[k + 1][col];
                u64 hA2 = *(const u64*)&s.h2t[k + 2][col];
                u64 hA3 = *(const u64*)&s.h2t[k + 3][col];
                u64 hB0 = *(const u64*)&s.h2t[k + 0][col + 64];
                u64 hB1 = *(const u64*)&s.h2t[k + 1][col + 64];
                u64 hB2 = *(const u64*)&s.h2t[k + 2][col + 64];
                u64 hB3 = *(const u64*)&s.h2t[k + 3][col + 64];
                #pragma unroll
                for (int r = 0; r < 3; r++) {
                    float4 w = __ldg(wr + r * 64 + k4);
                    u64 w0 = dup2(w.x), w1 = dup2(w.y), w2 = dup2(w.z), w3 = dup2(w.w);
                    acc[r][0] = ffma2(w0, hA0, acc[r][0]);
                    acc[r][0] = ffma2(w1, hA1, acc[r][0]);
                    acc[r][0] = ffma2(w2, hA2, acc[r][0]);
                    acc[r][0] = ffma2(w3, hA3, acc[r][0]);
                    acc[r][1] = ffma2(w0, hB0, acc[r][1]);
                    acc[r][1] = ffma2(w1, hB1, acc[r][1]);
                    acc[r][1] = ffma2(w2, hB2, acc[r][1]);
                    acc[r][1] = ffma2(w3, hB3, acc[r][1]);
                }
            }

            u64 xA = pack2(s.xc[col][c],      s.xc[col + 1][c]);
            u64 xB = pack2(s.xc[col + 64][c], s.xc[col + 65][c]);
            #pragma unroll
            for (int r = 0; r < 3; r++) {
                u64 b2v = dup2(__ldg(pw_b3 + c * 3 + r));
                oA[r] = ffma2(xA, add2(acc[r][0], b2v), oA[r]);
                oB[r] = ffma2(xB, add2(acc[r][1], b2v), oB[r]);
            }
        }

        #pragma unroll
        for (int r = 0; r < 3; r++) {
            float2 a = unpk(oA[r]);
            float2 b = unpk(oB[r]);
            s.u.red[warp][col][r]      = a.x;
            s.u.red[warp][col + 1][r]  = a.y;
            s.u.red[warp][col + 64][r] = b.x;
            s.u.red[warp][col + 65][r] = b.y;
        }
    }
    __syncthreads();

    // ---- cross-warp channel reduction + output ----
    {
        const int p = tid >> 2;
        const int r = tid & 3;
        if (r < 3) {
            float v = 0.f;
            #pragma unroll
            for (int w = 0; w < 16; w++) v += s.u.red[w][p][r];
            out[r * NPIX + pix0 + p] = v;
        }
    }
}

extern "C" void kernel_launch(void* const* d_in, const int* in_sizes, int n_in,
                              void* d_out, int out_size) {
    (void)in_sizes; (void)n_in; (void)out_size;
    const float* x      = (const float*)d_in[0];
    const float* pose   = (const float*)d_in[1];
    const int*   imY    = (const int*)  d_in[2];
    const int*   imX    = (const int*)  d_in[3];
    const float* sigmar = (const float*)d_in[4];
    const float* dw_w1  = (const float*)d_in[5];
    const float* dw_b1  = (const float*)d_in[6];
    const float* dw_w2  = (const float*)d_in[7];
    const float* dw_b2  = (const float*)d_in[8];
    const float* dw_w3  = (const float*)d_in[9];
    const float* dw_b3  = (const float*)d_in[10];
    const float* pw_w1  = (const float*)d_in[11];
    const float* pw_b1  = (const float*)d_in[12];
    const float* pw_w2  = (const float*)d_in[13];
    const float* pw_b2  = (const float*)d_in[14];
    const float* pw_w3  = (const float*)d_in[15];
    const float* pw_b3  = (const float*)d_in[16];
    float* out = (float*)d_out;

    const int tsmem = 64 * 257 * 4;
    cudaFuncSetAttribute(transpose_x_kernel,
                         cudaFuncAttributeMaxDynamicSharedMemorySize, tsmem);
    transpose_x_kernel<<<256, 256, tsmem>>>(x);

    const int smem = (int)sizeof(Smem);
    cudaFuncSetAttribute(biupsampler_fused,
                         cudaFuncAttributeMaxDynamicSharedMemorySize, smem);
    biupsampler_fused<<<NPIX / PPB, NTH, smem>>>(
        x, pose, imY, imX, sigmar,
        dw_w1, dw_b1, dw_w2, dw_b2, dw_w3, dw_b3,
        pw_w1, pw_b1, pw_w2, pw_b2, pw_w3, pw_b3,
        out);
}